// round 2
// baseline (speedup 1.0000x reference)
#include <cuda_runtime.h>
#include <cstdint>

// ---------------- problem dims ----------------
static constexpr int BATCH = 16;
static constexpr int HWD   = 64;
static constexpr int CH    = 256;           // Cin = Cout
static constexpr int KTOT  = 9 * CH;        // 2304
static constexpr int KCH   = 32;            // K per chunk
static constexpr int NCHUNK = KTOT / KCH;   // 72
static constexpr int AS    = 36;            // smem row stride (floats) -> conflict-free

// ---------------- device scratch ----------------
__device__ float g_K2[CH * CH];
__device__ float g_d[BATCH * CH];
__device__ float g_B[NCHUNK * CH * KCH];    // [chunk][co][k] tf32-rounded, packed

// smem layout (floats): s[256] | d[256] | A 2x(128*36) | B 2x(256*36)
static constexpr int SM_S = 0;
static constexpr int SM_D = 256;
static constexpr int SM_A = 512;
static constexpr int A_BUF = 128 * AS;      // 4608 floats
static constexpr int SM_B = SM_A + 2 * A_BUF;
static constexpr int B_BUF = 256 * AS;      // 9216 floats
static constexpr int SMEM_FLOATS = SM_B + 2 * B_BUF;       // 28160
static constexpr int SMEM_BYTES  = SMEM_FLOATS * 4;        // 112640

// ---------------- helpers ----------------
__device__ __forceinline__ float to_tf32(float v) {
    uint32_t u;
    asm("cvt.rna.tf32.f32 %0, %1;" : "=r"(u) : "f"(v));
    return __uint_as_float(u);
}
__device__ __forceinline__ uint32_t smem_u32(const void* p) {
    uint32_t a;
    asm("{ .reg .u64 t; cvta.to.shared.u64 t, %1; cvt.u32.u64 %0, t; }" : "=r"(a) : "l"(p));
    return a;
}
__device__ __forceinline__ void cp16(uint32_t dst_smem, const void* src) {
    asm volatile("cp.async.cg.shared.global [%0], [%1], 16;" :: "r"(dst_smem), "l"(src));
}
__device__ __forceinline__ void cp_commit() {
    asm volatile("cp.async.commit_group;" ::: "memory");
}
__device__ __forceinline__ void cp_wait0() {
    asm volatile("cp.async.wait_group 0;" ::: "memory");
}
__device__ __forceinline__ void mma_tf32(float* c, const uint32_t* a, const uint32_t* b) {
    asm volatile(
        "mma.sync.aligned.m16n8k8.row.col.f32.tf32.tf32.f32 "
        "{%0,%1,%2,%3}, {%4,%5,%6,%7}, {%8,%9}, {%0,%1,%2,%3};"
        : "+f"(c[0]), "+f"(c[1]), "+f"(c[2]), "+f"(c[3])
        : "r"(a[0]), "r"(a[1]), "r"(a[2]), "r"(a[3]), "r"(b[0]), "r"(b[1]));
}

// ---------------- prep kernels ----------------
__global__ void k2_kernel(const float* __restrict__ kern) {
    int co = threadIdx.x, ci = blockIdx.x;
    float acc = 0.f;
#pragma unroll
    for (int tap = 0; tap < 9; tap++) {
        float v = kern[(tap * CH + ci) * CH + co];
        acc += v * v;
    }
    g_K2[ci * CH + co] = acc;
}

__global__ void d_kernel(const float* __restrict__ style) {
    __shared__ float s2[CH];
    int b = blockIdx.x, t = threadIdx.x;
    float s = style[b * CH + t] + 1.0f;
    s2[t] = s * s;
    __syncthreads();
    float acc = 0.f;
#pragma unroll 8
    for (int ci = 0; ci < CH; ci++) acc += s2[ci] * g_K2[ci * CH + t];
    g_d[b * CH + t] = rsqrtf(acc + 1e-8f);
}

// pack kernel -> [chunk][co][k] tf32-rounded
__global__ void bprep_kernel(const float* __restrict__ kern) {
    int e = blockIdx.x * 256 + threadIdx.x;   // 589824
    int co = e & 255;
    int k  = e >> 8;                          // tap*256 + ci
    int chunk = k >> 5, kk = k & 31;
    g_B[(size_t)chunk * (CH * KCH) + co * KCH + kk] = to_tf32(kern[k * CH + co]);
}

// ---------------- main kernel ----------------
// 512 CTAs = 16 batches x 32 M-tiles. CTA: M=128 (2 rows x 64 w) x N=256, K=2304.
// 512 threads = 16 warps (4 M x 4 N), warp tile 32 x 64.
__global__ void __launch_bounds__(512, 1) conv_kernel(
    const float* __restrict__ x, const float* __restrict__ style, float* __restrict__ y) {
    extern __shared__ float sm[];
    float* s_s = sm + SM_S;
    float* s_d = sm + SM_D;
    float* sA  = sm + SM_A;
    float* sB  = sm + SM_B;
    const uint32_t sB_u32 = smem_u32(sB);

    const int tid  = threadIdx.x;
    const int lane = tid & 31;
    const int wid  = tid >> 5;
    const int b    = blockIdx.x >> 5;
    const int mt   = blockIdx.x & 31;
    const int h0   = mt * 2;

    if (tid < CH) {
        s_s[tid] = style[b * CH + tid] + 1.0f;
        s_d[tid] = g_d[b * CH + tid];
    }
    __syncthreads();

    const float* xb = x + (size_t)b * HWD * HWD * CH;

    // per-thread A staging state
    float4 ar0, ar1;
    int a_ci0 = 0;
    const int r0 = (tid) >> 3,        v0 = tid & 7;          // j=0 element
    const int r1 = (512 + tid) >> 3,  v1 = tid & 7;          // j=1 element
    const int mr0 = r0 >> 6, wq0 = r0 & 63;
    const int mr1 = r1 >> 6, wq1 = r1 & 63;

#define LOAD_A(chunk)                                                              \
    {                                                                              \
        int tap = (chunk) >> 3, sub = (chunk) & 7;                                 \
        int kh = tap / 3 - 1, kw = tap % 3 - 1;                                    \
        a_ci0 = sub * KCH;                                                         \
        int hi0 = h0 + mr0 + kh, wi0 = wq0 + kw;                                   \
        int hi1 = h0 + mr1 + kh, wi1 = wq1 + kw;                                   \
        ar0 = make_float4(0.f, 0.f, 0.f, 0.f);                                     \
        ar1 = make_float4(0.f, 0.f, 0.f, 0.f);                                     \
        if ((unsigned)hi0 < (unsigned)HWD && (unsigned)wi0 < (unsigned)HWD)        \
            ar0 = *(const float4*)(xb + ((size_t)(hi0 * HWD + wi0)) * CH + a_ci0 + v0 * 4); \
        if ((unsigned)hi1 < (unsigned)HWD && (unsigned)wi1 < (unsigned)HWD)        \
            ar1 = *(const float4*)(xb + ((size_t)(hi1 * HWD + wi1)) * CH + a_ci0 + v1 * 4); \
    }

#define STORE_A(sbuf)                                                              \
    {                                                                              \
        float* abuf = sA + (sbuf) * A_BUF;                                         \
        float4 sv0 = *(const float4*)(s_s + a_ci0 + v0 * 4);                       \
        float4 sv1 = *(const float4*)(s_s + a_ci0 + v1 * 4);                       \
        float4 o0, o1;                                                             \
        o0.x = to_tf32(ar0.x * sv0.x); o0.y = to_tf32(ar0.y * sv0.y);              \
        o0.z = to_tf32(ar0.z * sv0.z); o0.w = to_tf32(ar0.w * sv0.w);              \
        o1.x = to_tf32(ar1.x * sv1.x); o1.y = to_tf32(ar1.y * sv1.y);              \
        o1.z = to_tf32(ar1.z * sv1.z); o1.w = to_tf32(ar1.w * sv1.w);              \
        *(float4*)(abuf + r0 * AS + v0 * 4) = o0;                                  \
        *(float4*)(abuf + r1 * AS + v1 * 4) = o1;                                  \
    }

#define LOAD_B(chunk, sbuf)                                                        \
    {                                                                              \
        const float* gb = g_B + (size_t)(chunk) * (CH * KCH);                      \
        uint32_t base = sB_u32 + (uint32_t)(sbuf) * (B_BUF * 4);                   \
        _Pragma("unroll")                                                          \
        for (int j = 0; j < 4; j++) {                                              \
            int u = j * 512 + tid;                                                 \
            int row = u >> 3, seg = u & 7;                                         \
            cp16(base + (uint32_t)(row * (AS * 4) + seg * 16), gb + u * 4);        \
        }                                                                          \
        cp_commit();                                                               \
    }

    // warp tiling
    const int wm = wid & 3, wn = wid >> 2;
    const int m0 = wm * 32, n0 = wn * 64;
    const int gi = lane >> 2, ti = lane & 3;

    float acc[2][8][4];
#pragma unroll
    for (int mi = 0; mi < 2; mi++)
#pragma unroll
        for (int ni = 0; ni < 8; ni++)
#pragma unroll
            for (int c = 0; c < 4; c++) acc[mi][ni][c] = 0.f;

    // prologue
    LOAD_A(0);
    LOAD_B(0, 0);

    for (int i = 0; i < NCHUNK; i++) {
        const int s = i & 1;
        STORE_A(s);
        if (i + 1 < NCHUNK) LOAD_A(i + 1);
        cp_wait0();
        __syncthreads();
        if (i + 1 < NCHUNK) LOAD_B(i + 1, s ^ 1);

        const float* A = sA + s * A_BUF;
        const float* Bm = sB + s * B_BUF;
#pragma unroll
        for (int kf = 0; kf < 4; kf++) {
            const int k0 = kf * 8;
            uint32_t bf[8][2];
#pragma unroll
            for (int ni = 0; ni < 8; ni++) {
                const float* bp = Bm + (n0 + ni * 8 + gi) * AS + k0 + ti;
                bf[ni][0] = __float_as_uint(bp[0]);
                bf[ni][1] = __float_as_uint(bp[4]);
            }
#pragma unroll
            for (int mi = 0; mi < 2; mi++) {
                const float* ap = A + (m0 + mi * 16 + gi) * AS + k0 + ti;
                uint32_t af[4];
                af[0] = __float_as_uint(ap[0]);
                af[1] = __float_as_uint(ap[8 * AS]);
                af[2] = __float_as_uint(ap[4]);
                af[3] = __float_as_uint(ap[8 * AS + 4]);
#pragma unroll
                for (int ni = 0; ni < 8; ni++) mma_tf32(acc[mi][ni], af, bf[ni]);
            }
        }
        // note: next iteration's STORE_A has implicit WAR safety via the
        // __syncthreads() above (all reads of buf s finished by then).
    }

    // ---- epilogue: demodulate + store NHWC ----
#pragma unroll
    for (int mi = 0; mi < 2; mi++) {
        const int ma = m0 + mi * 16 + gi;       // rows ma and ma+8
        const int mb = ma + 8;
        const int mra = ma >> 6, wqa = ma & 63;
        const int mrb = mb >> 6, wqb = mb & 63;
        float* ya = y + (((size_t)b * HWD + (h0 + mra)) * HWD + wqa) * CH;
        float* yb2 = y + (((size_t)b * HWD + (h0 + mrb)) * HWD + wqb) * CH;
#pragma unroll
        for (int ni = 0; ni < 8; ni++) {
            const int col = n0 + ni * 8 + 2 * ti;
            const float d0 = s_d[col], d1 = s_d[col + 1];
            float2 oa, ob;
            oa.x = acc[mi][ni][0] * d0; oa.y = acc[mi][ni][1] * d1;
            ob.x = acc[mi][ni][2] * d0; ob.y = acc[mi][ni][3] * d1;
            *(float2*)(ya + col)  = oa;
            *(float2*)(yb2 + col) = ob;
        }
    }
#undef LOAD_A
#undef STORE_A
#undef LOAD_B
}

// ---------------- launch ----------------
extern "C" void kernel_launch(void* const* d_in, const int* in_sizes, int n_in,
                              void* d_out, int out_size) {
    const float* x     = (const float*)d_in[0];   // [16,64,64,256]
    const float* style = (const float*)d_in[1];   // [16,256]
    const float* kern  = (const float*)d_in[2];   // [3,3,256,256]
    float* y = (float*)d_out;                     // [16,64,64,256]

    static bool attr_set = false;
    if (!attr_set) {
        cudaFuncSetAttribute(conv_kernel, cudaFuncAttributeMaxDynamicSharedMemorySize, SMEM_BYTES);
        attr_set = true;
    }

    k2_kernel<<<CH, CH>>>(kern);
    d_kernel<<<BATCH, CH>>>(style);
    bprep_kernel<<<KTOT, 256>>>(kern);
    conv_kernel<<<BATCH * 32, 512, SMEM_BYTES>>>(x, style, y);
}

// round 3
// speedup vs baseline: 1.0003x; 1.0003x over previous
#include <cuda_runtime.h>
#include <cstdint>

// ---------------- problem dims ----------------
static constexpr int BATCH = 16;
static constexpr int HWD   = 64;
static constexpr int CH    = 256;           // Cin = Cout
static constexpr int KTOT  = 9 * CH;        // 2304
static constexpr int KCH   = 32;            // K per chunk
static constexpr int NCHUNK = KTOT / KCH;   // 72
static constexpr int AS    = 36;            // smem row stride (floats) -> conflict-free

// CTA tile: M=128, N=128. 256 threads = 8 warps (4 M x 2 N), warp tile 32x64.
static constexpr int CTA_N = 128;

// ---------------- device scratch ----------------
__device__ float g_K2[CH * CH];
__device__ float g_d[BATCH * CH];
__device__ float g_B[NCHUNK * CH * KCH];    // [chunk][co][kperm] tf32-rounded

// smem layout (floats): s[256] | d[256] | A 2x(128*36) | B 2x(128*36)
static constexpr int SM_S = 0;
static constexpr int SM_D = 256;
static constexpr int SM_A = 512;
static constexpr int A_BUF = 128 * AS;      // 4608 floats
static constexpr int SM_B = SM_A + 2 * A_BUF;
static constexpr int B_BUF = 128 * AS;      // 4608 floats
static constexpr int SMEM_FLOATS = SM_B + 2 * B_BUF;   // 18944
static constexpr int SMEM_BYTES  = SMEM_FLOATS * 4;    // 75776 -> 2 CTAs/SM

// ---------------- helpers ----------------
__device__ __forceinline__ float to_tf32(float v) {
    uint32_t u;
    asm("cvt.rna.tf32.f32 %0, %1;" : "=r"(u) : "f"(v));
    return __uint_as_float(u);
}
__device__ __forceinline__ uint32_t smem_u32(const void* p) {
    uint32_t a;
    asm("{ .reg .u64 t; cvta.to.shared.u64 t, %1; cvt.u32.u64 %0, t; }" : "=r"(a) : "l"(p));
    return a;
}
__device__ __forceinline__ void cp16(uint32_t dst_smem, const void* src) {
    asm volatile("cp.async.cg.shared.global [%0], [%1], 16;" :: "r"(dst_smem), "l"(src));
}
__device__ __forceinline__ void cp_commit() {
    asm volatile("cp.async.commit_group;" ::: "memory");
}
__device__ __forceinline__ void cp_wait0() {
    asm volatile("cp.async.wait_group 0;" ::: "memory");
}
__device__ __forceinline__ void mma_tf32(float* c, const uint32_t* a, const uint32_t* b) {
    asm volatile(
        "mma.sync.aligned.m16n8k8.row.col.f32.tf32.tf32.f32 "
        "{%0,%1,%2,%3}, {%4,%5,%6,%7}, {%8,%9}, {%0,%1,%2,%3};"
        : "+f"(c[0]), "+f"(c[1]), "+f"(c[2]), "+f"(c[3])
        : "r"(a[0]), "r"(a[1]), "r"(a[2]), "r"(a[3]), "r"(b[0]), "r"(b[1]));
}

// ---------------- prep kernels ----------------
__global__ void k2_kernel(const float* __restrict__ kern) {
    int co = threadIdx.x, ci = blockIdx.x;
    float acc = 0.f;
#pragma unroll
    for (int tap = 0; tap < 9; tap++) {
        float v = kern[(tap * CH + ci) * CH + co];
        acc += v * v;
    }
    g_K2[ci * CH + co] = acc;
}

__global__ void d_kernel(const float* __restrict__ style) {
    __shared__ float s2[CH];
    int b = blockIdx.x, t = threadIdx.x;
    float s = style[b * CH + t] + 1.0f;
    s2[t] = s * s;
    __syncthreads();
    float acc = 0.f;
#pragma unroll 8
    for (int ci = 0; ci < CH; ci++) acc += s2[ci] * g_K2[ci * CH + t];
    g_d[b * CH + t] = rsqrtf(acc + 1e-8f);
}

// pack kernel -> [chunk][co][kperm] tf32-rounded.
// K-permutation p = 8*(k&3) + (k>>2): makes each mma thread's 8 B values per
// row contiguous -> LDS.128 fragment loads.
__global__ void bprep_kernel(const float* __restrict__ kern) {
    int e = blockIdx.x * 256 + threadIdx.x;   // 589824
    int co = e & 255;
    int k  = e >> 8;                          // tap*256 + ci
    int chunk = k >> 5, kk = k & 31;
    int p = 8 * (kk & 3) + (kk >> 2);
    g_B[(size_t)chunk * (CH * KCH) + co * KCH + p] = to_tf32(kern[k * CH + co]);
}

// ---------------- main kernel ----------------
// Grid: 1024 CTAs = 16 b x 32 mtiles x 2 ntiles. CTA: M=128 x N=128, K=2304.
// 256 threads = 8 warps (4 M x 2 N), warp tile 32 x 64. 2 CTAs/SM.
__global__ void __launch_bounds__(256, 2) conv_kernel(
    const float* __restrict__ x, const float* __restrict__ style, float* __restrict__ y) {
    extern __shared__ float sm[];
    float* s_s = sm + SM_S;
    float* s_d = sm + SM_D;
    float* sA  = sm + SM_A;
    float* sB  = sm + SM_B;
    const uint32_t sB_u32 = smem_u32(sB);

    const int tid  = threadIdx.x;
    const int lane = tid & 31;
    const int wid  = tid >> 5;
    const int b    = blockIdx.x >> 6;
    const int mt   = (blockIdx.x >> 1) & 31;
    const int nt   = blockIdx.x & 1;
    const int h0   = mt * 2;
    const int co0  = nt * CTA_N;

    if (tid < CH) s_s[tid] = style[b * CH + tid] + 1.0f;
    if (tid < CTA_N) s_d[tid] = g_d[b * CH + co0 + tid];
    __syncthreads();

    const float* xb = x + (size_t)b * HWD * HWD * CH;

    // A staging: 128 rows x 32 floats = 1024 float4, 4 per thread
    float4 ar[4];
    int a_ci0 = 0;
    int rr[4], vv[4], mrr[4], wqq[4];
#pragma unroll
    for (int j = 0; j < 4; j++) {
        int g = j * 256 + tid;
        rr[j] = g >> 3; vv[j] = g & 7;
        mrr[j] = rr[j] >> 6; wqq[j] = rr[j] & 63;
    }

#define LOAD_A(chunk)                                                              \
    {                                                                              \
        int tap = (chunk) >> 3, sub = (chunk) & 7;                                 \
        int kh = tap / 3 - 1, kw = tap % 3 - 1;                                    \
        a_ci0 = sub * KCH;                                                         \
        _Pragma("unroll")                                                          \
        for (int j = 0; j < 4; j++) {                                              \
            int hi = h0 + mrr[j] + kh, wi = wqq[j] + kw;                           \
            ar[j] = make_float4(0.f, 0.f, 0.f, 0.f);                               \
            if ((unsigned)hi < (unsigned)HWD && (unsigned)wi < (unsigned)HWD)      \
                ar[j] = *(const float4*)(xb + ((size_t)(hi * HWD + wi)) * CH + a_ci0 + vv[j] * 4); \
        }                                                                          \
    }

#define STORE_A(sbuf)                                                              \
    {                                                                              \
        float* abuf = sA + (sbuf) * A_BUF;                                         \
        _Pragma("unroll")                                                          \
        for (int j = 0; j < 4; j++) {                                              \
            float4 sv = *(const float4*)(s_s + a_ci0 + vv[j] * 4);                 \
            float4 o;                                                              \
            o.x = to_tf32(ar[j].x * sv.x); o.y = to_tf32(ar[j].y * sv.y);          \
            o.z = to_tf32(ar[j].z * sv.z); o.w = to_tf32(ar[j].w * sv.w);          \
            *(float4*)(abuf + rr[j] * AS + vv[j] * 4) = o;                         \
        }                                                                          \
    }

#define LOAD_B(chunk, sbuf)                                                        \
    {                                                                              \
        const float* gb = g_B + (size_t)(chunk) * (CH * KCH) + (size_t)co0 * KCH;  \
        uint32_t base = sB_u32 + (uint32_t)(sbuf) * (B_BUF * 4);                   \
        _Pragma("unroll")                                                          \
        for (int j = 0; j < 4; j++) {                                              \
            int u = j * 256 + tid;                                                 \
            int row = u >> 3, seg = u & 7;                                         \
            cp16(base + (uint32_t)(row * (AS * 4) + seg * 16), gb + u * 4);        \
        }                                                                          \
        cp_commit();                                                               \
    }

    // warp tiling: 4 wm x 2 wn, warp tile 32 x 64
    const int wm = wid & 3, wn = wid >> 2;
    const int m0 = wm * 32, n0 = wn * 64;
    const int gi = lane >> 2, ti = lane & 3;

    float acc[2][8][4];
#pragma unroll
    for (int mi = 0; mi < 2; mi++)
#pragma unroll
        for (int ni = 0; ni < 8; ni++)
#pragma unroll
            for (int c = 0; c < 4; c++) acc[mi][ni][c] = 0.f;

    LOAD_A(0);
    LOAD_B(0, 0);

    for (int i = 0; i < NCHUNK; i++) {
        const int s = i & 1;
        STORE_A(s);
        if (i + 1 < NCHUNK) LOAD_A(i + 1);
        cp_wait0();
        __syncthreads();
        if (i + 1 < NCHUNK) LOAD_B(i + 1, s ^ 1);

        const float* A  = sA + s * A_BUF;
        const float* Bm = sB + s * B_BUF;
#pragma unroll
        for (int half = 0; half < 2; half++) {
            // B fragments: one float4 per n-row covers both kf of this half
            // (permuted layout: phys 8*ti+half*4 .. +3 = logical k
            //  {ti,ti+4} for kf=2*half and {ti+8+..} for kf=2*half+1)
            float4 bq[8];
#pragma unroll
            for (int ni = 0; ni < 8; ni++)
                bq[ni] = *(const float4*)(Bm + (n0 + ni * 8 + gi) * AS + 8 * ti + half * 4);
#pragma unroll
            for (int kf2 = 0; kf2 < 2; kf2++) {
                const int k0 = (half * 2 + kf2) * 8;
#pragma unroll
                for (int mi = 0; mi < 2; mi++) {
                    const float* ap = A + (m0 + mi * 16 + gi) * AS + k0 + ti;
                    uint32_t af[4];
                    af[0] = __float_as_uint(ap[0]);
                    af[1] = __float_as_uint(ap[8 * AS]);
                    af[2] = __float_as_uint(ap[4]);
                    af[3] = __float_as_uint(ap[8 * AS + 4]);
#pragma unroll
                    for (int ni = 0; ni < 8; ni++) {
                        uint32_t bf[2];
                        bf[0] = __float_as_uint(kf2 ? bq[ni].z : bq[ni].x);
                        bf[1] = __float_as_uint(kf2 ? bq[ni].w : bq[ni].y);
                        mma_tf32(acc[mi][ni], af, bf);
                    }
                }
            }
        }
    }

    // ---- epilogue: demodulate + store NHWC ----
#pragma unroll
    for (int mi = 0; mi < 2; mi++) {
        const int ma = m0 + mi * 16 + gi;
        const int mb = ma + 8;
        const int mra = ma >> 6, wqa = ma & 63;
        const int mrb = mb >> 6, wqb = mb & 63;
        float* ya  = y + (((size_t)b * HWD + (h0 + mra)) * HWD + wqa) * CH + co0;
        float* yb2 = y + (((size_t)b * HWD + (h0 + mrb)) * HWD + wqb) * CH + co0;
#pragma unroll
        for (int ni = 0; ni < 8; ni++) {
            const int col = n0 + ni * 8 + 2 * ti;   // local co
            const float d0 = s_d[col], d1 = s_d[col + 1];
            float2 oa, ob;
            oa.x = acc[mi][ni][0] * d0; oa.y = acc[mi][ni][1] * d1;
            ob.x = acc[mi][ni][2] * d0; ob.y = acc[mi][ni][3] * d1;
            *(float2*)(ya + col)  = oa;
            *(float2*)(yb2 + col) = ob;
        }
    }
#undef LOAD_A
#undef STORE_A
#undef LOAD_B
}

// ---------------- launch ----------------
extern "C" void kernel_launch(void* const* d_in, const int* in_sizes, int n_in,
                              void* d_out, int out_size) {
    const float* x     = (const float*)d_in[0];   // [16,64,64,256]
    const float* style = (const float*)d_in[1];   // [16,256]
    const float* kern  = (const float*)d_in[2];   // [3,3,256,256]
    float* y = (float*)d_out;                     // [16,64,64,256]

    static bool attr_set = false;
    if (!attr_set) {
        cudaFuncSetAttribute(conv_kernel, cudaFuncAttributeMaxDynamicSharedMemorySize, SMEM_BYTES);
        attr_set = true;
    }

    k2_kernel<<<CH, CH>>>(kern);
    d_kernel<<<BATCH, CH>>>(style);
    bprep_kernel<<<KTOT, 256>>>(kern);
    conv_kernel<<<BATCH * 32 * 2, 256, SMEM_BYTES>>>(x, style, y);
}

// round 4
// speedup vs baseline: 1.2462x; 1.2458x over previous
#include <cuda_runtime.h>
#include <cstdint>

// ---------------- problem dims ----------------
static constexpr int BATCH = 16;
static constexpr int HWD   = 64;
static constexpr int CH    = 256;           // Cin = Cout
static constexpr int KTOT  = 9 * CH;        // 2304
static constexpr int KCH   = 32;            // K per chunk
static constexpr int NCHUNK = KTOT / KCH;   // 72
static constexpr int AS    = 36;            // smem row stride (floats) -> conflict-free

static constexpr int CTA_N = 128;

// ---------------- device scratch ----------------
__device__ float g_K2[CH * CH];
__device__ float g_d[BATCH * CH];
__device__ float g_B[NCHUNK * CH * KCH];    // [chunk][co][kperm] tf32-rounded

// smem layout (floats): s[256] | d[256] | A 2x(128*36) | B 2x(128*36)
static constexpr int SM_S = 0;
static constexpr int SM_D = 256;
static constexpr int SM_A = 512;
static constexpr int A_BUF = 128 * AS;      // 4608 floats
static constexpr int SM_B = SM_A + 2 * A_BUF;
static constexpr int B_BUF = 128 * AS;      // 4608 floats
static constexpr int SMEM_FLOATS = SM_B + 2 * B_BUF;   // 18944
static constexpr int SMEM_BYTES  = SMEM_FLOATS * 4;    // 75776 -> 2 CTAs/SM

// ---------------- helpers ----------------
__device__ __forceinline__ float to_tf32(float v) {
    uint32_t u;
    asm("cvt.rna.tf32.f32 %0, %1;" : "=r"(u) : "f"(v));
    return __uint_as_float(u);
}
__device__ __forceinline__ uint32_t smem_u32(const void* p) {
    uint32_t a;
    asm("{ .reg .u64 t; cvta.to.shared.u64 t, %1; cvt.u32.u64 %0, t; }" : "=r"(a) : "l"(p));
    return a;
}
__device__ __forceinline__ void cp16(uint32_t dst_smem, const void* src) {
    asm volatile("cp.async.cg.shared.global [%0], [%1], 16;" :: "r"(dst_smem), "l"(src));
}
__device__ __forceinline__ void cp_commit() {
    asm volatile("cp.async.commit_group;" ::: "memory");
}
__device__ __forceinline__ void cp_wait0() {
    asm volatile("cp.async.wait_group 0;" ::: "memory");
}
__device__ __forceinline__ void mma_tf32(float* c, const uint32_t* a, const uint32_t* b) {
    asm volatile(
        "mma.sync.aligned.m16n8k8.row.col.f32.tf32.tf32.f32 "
        "{%0,%1,%2,%3}, {%4,%5,%6,%7}, {%8,%9}, {%0,%1,%2,%3};"
        : "+f"(c[0]), "+f"(c[1]), "+f"(c[2]), "+f"(c[3])
        : "r"(a[0]), "r"(a[1]), "r"(a[2]), "r"(a[3]), "r"(b[0]), "r"(b[1]));
}

// ---------------- prep kernels ----------------
__global__ void k2_kernel(const float* __restrict__ kern) {
    int co = threadIdx.x, ci = blockIdx.x;
    float acc = 0.f;
#pragma unroll
    for (int tap = 0; tap < 9; tap++) {
        float v = kern[(tap * CH + ci) * CH + co];
        acc += v * v;
    }
    g_K2[ci * CH + co] = acc;
}

__global__ void d_kernel(const float* __restrict__ style) {
    __shared__ float s2[CH];
    int b = blockIdx.x, t = threadIdx.x;
    float s = style[b * CH + t] + 1.0f;
    s2[t] = s * s;
    __syncthreads();
    float acc = 0.f;
#pragma unroll 8
    for (int ci = 0; ci < CH; ci++) acc += s2[ci] * g_K2[ci * CH + t];
    g_d[b * CH + t] = rsqrtf(acc + 1e-8f);
}

// pack kernel -> [chunk][co][kperm] tf32-rounded.
// K-permutation p = 8*(k&3) + (k>>2): each mma thread's per-half B values
// land contiguous -> LDS.128 fragment loads.
__global__ void bprep_kernel(const float* __restrict__ kern) {
    int e = blockIdx.x * 256 + threadIdx.x;   // 589824
    int co = e & 255;
    int k  = e >> 8;                          // tap*256 + ci
    int chunk = k >> 5, kk = k & 31;
    int p = 8 * (kk & 3) + (kk >> 2);
    g_B[(size_t)chunk * (CH * KCH) + co * KCH + p] = to_tf32(kern[k * CH + co]);
}

// ---------------- main kernel ----------------
// Grid: 1024 CTAs = 16 b x 32 mtiles x 2 ntiles. CTA: M=128 x N=128, K=2304.
// 128 threads = 4 warps (2 M x 2 N), warp tile 64 x 64. 2 CTAs/SM.
__global__ void __launch_bounds__(128, 2) conv_kernel(
    const float* __restrict__ x, const float* __restrict__ style, float* __restrict__ y) {
    extern __shared__ float sm[];
    float* s_s = sm + SM_S;
    float* s_d = sm + SM_D;
    float* sA  = sm + SM_A;
    float* sB  = sm + SM_B;
    const uint32_t sB_u32 = smem_u32(sB);

    const int tid  = threadIdx.x;
    const int lane = tid & 31;
    const int wid  = tid >> 5;
    const int b    = blockIdx.x >> 6;
    const int mt   = (blockIdx.x >> 1) & 31;
    const int nt   = blockIdx.x & 1;
    const int h0   = mt * 2;
    const int co0  = nt * CTA_N;

    for (int i = tid; i < CH; i += 128) s_s[i] = style[b * CH + i] + 1.0f;
    if (tid < CTA_N) s_d[tid] = g_d[b * CH + co0 + tid];
    __syncthreads();

    const float* xb = x + (size_t)b * HWD * HWD * CH;

    // A staging: 128 rows x 32 floats = 1024 float4, 8 per thread
    float4 ar[8];
    int a_ci0 = 0;
    const int r_base = tid >> 3;          // row for j: r_base + j*16
    const int v_     = tid & 7;

#define LOAD_A(chunk)                                                              \
    {                                                                              \
        int tap = (chunk) >> 3, sub = (chunk) & 7;                                 \
        int kh = tap / 3 - 1, kw = tap % 3 - 1;                                    \
        a_ci0 = sub * KCH;                                                         \
        _Pragma("unroll")                                                          \
        for (int j = 0; j < 8; j++) {                                              \
            int r = r_base + j * 16;                                               \
            int hi = h0 + (r >> 6) + kh, wi = (r & 63) + kw;                       \
            ar[j] = make_float4(0.f, 0.f, 0.f, 0.f);                               \
            if ((unsigned)hi < (unsigned)HWD && (unsigned)wi < (unsigned)HWD)      \
                ar[j] = *(const float4*)(xb + ((size_t)(hi * HWD + wi)) * CH + a_ci0 + v_ * 4); \
        }                                                                          \
    }

#define STORE_A(sbuf)                                                              \
    {                                                                              \
        float* abuf = sA + (sbuf) * A_BUF;                                         \
        float4 sv = *(const float4*)(s_s + a_ci0 + v_ * 4);                        \
        _Pragma("unroll")                                                          \
        for (int j = 0; j < 8; j++) {                                              \
            float4 o;                                                              \
            o.x = to_tf32(ar[j].x * sv.x); o.y = to_tf32(ar[j].y * sv.y);          \
            o.z = to_tf32(ar[j].z * sv.z); o.w = to_tf32(ar[j].w * sv.w);          \
            *(float4*)(abuf + (r_base + j * 16) * AS + v_ * 4) = o;                \
        }                                                                          \
    }

#define LOAD_B(chunk, sbuf)                                                        \
    {                                                                              \
        const float* gb = g_B + (size_t)(chunk) * (CH * KCH) + (size_t)co0 * KCH;  \
        uint32_t base = sB_u32 + (uint32_t)(sbuf) * (B_BUF * 4);                   \
        _Pragma("unroll")                                                          \
        for (int j = 0; j < 8; j++) {                                              \
            int u = j * 128 + tid;                                                 \
            int row = u >> 3, seg = u & 7;                                         \
            cp16(base + (uint32_t)(row * (AS * 4) + seg * 16), gb + u * 4);        \
        }                                                                          \
        cp_commit();                                                               \
    }

    // warp tiling: 2 wm x 2 wn, warp tile 64 x 64
    const int wm = wid & 1, wn = wid >> 1;
    const int m0 = wm * 64, n0 = wn * 64;
    const int gi = lane >> 2, ti = lane & 3;

    float acc[4][8][4];
#pragma unroll
    for (int mi = 0; mi < 4; mi++)
#pragma unroll
        for (int ni = 0; ni < 8; ni++)
#pragma unroll
            for (int c = 0; c < 4; c++) acc[mi][ni][c] = 0.f;

    LOAD_A(0);
    LOAD_B(0, 0);

// one half = 8 B LDS.128 + 2 kf x 4 mi x (4 A LDS.32 + 8 HMMA)
#define MMA_HALF(half)                                                             \
    {                                                                              \
        float4 bq[8];                                                              \
        _Pragma("unroll")                                                          \
        for (int ni = 0; ni < 8; ni++)                                             \
            bq[ni] = *(const float4*)(Bw + ni * 8 * AS + (half) * 4);              \
        _Pragma("unroll")                                                          \
        for (int kf2 = 0; kf2 < 2; kf2++) {                                        \
            const int k0 = ((half) * 2 + kf2) * 8;                                 \
            _Pragma("unroll")                                                      \
            for (int mi = 0; mi < 4; mi++) {                                       \
                const float* ap = Aw + mi * (16 * AS) + k0;                        \
                uint32_t af[4];                                                    \
                af[0] = __float_as_uint(ap[0]);                                    \
                af[1] = __float_as_uint(ap[8 * AS]);                               \
                af[2] = __float_as_uint(ap[4]);                                    \
                af[3] = __float_as_uint(ap[8 * AS + 4]);                           \
                _Pragma("unroll")                                                  \
                for (int ni = 0; ni < 8; ni++) {                                   \
                    uint32_t bf[2];                                                \
                    bf[0] = __float_as_uint(kf2 ? bq[ni].z : bq[ni].x);            \
                    bf[1] = __float_as_uint(kf2 ? bq[ni].w : bq[ni].y);            \
                    mma_tf32(acc[mi][ni], af, bf);                                 \
                }                                                                  \
            }                                                                      \
        }                                                                          \
    }

    for (int i = 0; i < NCHUNK; i++) {
        const int s = i & 1;
        STORE_A(s);
        cp_wait0();
        __syncthreads();
        if (i + 1 < NCHUNK) LOAD_B(i + 1, s ^ 1);

        const float* Aw = sA + s * A_BUF + (m0 + gi) * AS + ti;
        const float* Bw = sB + s * B_BUF + (n0 + gi) * AS + 8 * ti;

        MMA_HALF(0)
        if (i + 1 < NCHUNK) LOAD_A(i + 1);   // LDG latency hidden under half 1
        MMA_HALF(1)
    }

    // ---- epilogue: demodulate + store NHWC ----
#pragma unroll
    for (int mi = 0; mi < 4; mi++) {
        const int ma = m0 + mi * 16 + gi;
        const int mb = ma + 8;
        float* ya  = y + (((size_t)b * HWD + (h0 + (ma >> 6))) * HWD + (ma & 63)) * CH + co0;
        float* yb2 = y + (((size_t)b * HWD + (h0 + (mb >> 6))) * HWD + (mb & 63)) * CH + co0;
#pragma unroll
        for (int ni = 0; ni < 8; ni++) {
            const int col = n0 + ni * 8 + 2 * ti;   // local co
            const float d0 = s_d[col], d1 = s_d[col + 1];
            float2 oa, ob;
            oa.x = acc[mi][ni][0] * d0; oa.y = acc[mi][ni][1] * d1;
            ob.x = acc[mi][ni][2] * d0; ob.y = acc[mi][ni][3] * d1;
            *(float2*)(ya + col)  = oa;
            *(float2*)(yb2 + col) = ob;
        }
    }
#undef LOAD_A
#undef STORE_A
#undef LOAD_B
#undef MMA_HALF
}

// ---------------- launch ----------------
extern "C" void kernel_launch(void* const* d_in, const int* in_sizes, int n_in,
                              void* d_out, int out_size) {
    const float* x     = (const float*)d_in[0];   // [16,64,64,256]
    const float* style = (const float*)d_in[1];   // [16,256]
    const float* kern  = (const float*)d_in[2];   // [3,3,256,256]
    float* y = (float*)d_out;                     // [16,64,64,256]

    static bool attr_set = false;
    if (!attr_set) {
        cudaFuncSetAttribute(conv_kernel, cudaFuncAttributeMaxDynamicSharedMemorySize, SMEM_BYTES);
        attr_set = true;
    }

    k2_kernel<<<CH, CH>>>(kern);
    d_kernel<<<BATCH, CH>>>(style);
    bprep_kernel<<<KTOT, 256>>>(kern);
    conv_kernel<<<BATCH * 32 * 2, 128, SMEM_BYTES>>>(x, style, y);
}